// round 13
// baseline (speedup 1.0000x reference)
#include <cuda_runtime.h>

// Problem constants
#define NB   8
#define TT   2048
#define CC   512
#define MTOT (NB*TT)        // 16384

// Scratch (device globals -- no runtime allocation allowed)
__device__ float g_q[MTOT*CC];
__device__ float g_k[MTOT*CC];
__device__ float g_v[MTOT*CC];
__device__ float g_s[(size_t)NB*TT*TT];   // holds E = exp(scaled scores)

// ---------------------------------------------------------------------------
// mma.sync tf32 (fp32 operands fed raw: HW truncates low mantissa bits)
// ---------------------------------------------------------------------------
__device__ __forceinline__ void mma8(float* c, const unsigned* a, const unsigned* b) {
    asm volatile(
        "mma.sync.aligned.m16n8k8.row.col.f32.tf32.tf32.f32 "
        "{%0,%1,%2,%3}, {%4,%5,%6,%7}, {%8,%9}, {%0,%1,%2,%3};\n"
        : "+f"(c[0]), "+f"(c[1]), "+f"(c[2]), "+f"(c[3])
        : "r"(a[0]), "r"(a[1]), "r"(a[2]), "r"(a[3]), "r"(b[0]), "r"(b[1]));
}

#define CP16(dst, src) \
    asm volatile("cp.async.cg.shared.global [%0], [%1], 16;\n" :: "r"(dst), "l"(src))
#define CPCOMMIT() asm volatile("cp.async.commit_group;\n" ::: "memory")
#define CPWAIT1()  asm volatile("cp.async.wait_group 1;\n" ::: "memory")

// ---------------------------------------------------------------------------
// Tiling: CTA = 128x128, BK = 16, 3-stage cp.async ring (wait_group 1 keeps
// two tile-loads in flight behind compute; every iteration commits a group --
// possibly empty -- so the wait depth is always correct).
// 8 warps in 4(m) x 2(n); warp tile 32x64 = 2 m-frags x 8 n-frags (m16n8k8).
// A tiles: [3][128][20] fp32 (pitch 20 -> conflict-free frag LDS).
// B tiles: KN [3][16][136] (proj/AV) or NK [3][128][20] (score).
// ---------------------------------------------------------------------------
#define A_STRIDE (128*20)
#define B_STRIDE (16*136)
#define PROJ_SMEM  ((3*A_STRIDE + 3*B_STRIDE) * 4)
#define SCORE_SMEM ((3*A_STRIDE * 2) * 4)
#define AV_SMEM    PROJ_SMEM

extern __shared__ float dynsmem[];

#define DECL_TILE_STATE()                                                     \
    const int tid = threadIdx.x;                                              \
    const int wid = tid >> 5, lane = tid & 31;                                \
    const int wm = wid & 3, wn = wid >> 2;                                    \
    const int gid = lane >> 2, tig = lane & 3;                                \
    float acc[2][8][4];                                                       \
    _Pragma("unroll")                                                         \
    for (int mf = 0; mf < 2; mf++)                                            \
        _Pragma("unroll")                                                     \
        for (int nf = 0; nf < 8; nf++)                                        \
            _Pragma("unroll")                                                 \
            for (int q = 0; q < 4; q++) acc[mf][nf][q] = 0.f;

#define BKN(B, k, n) __float_as_uint(B[k][n])
#define BNK(B, k, n) __float_as_uint(B[n][k])

#define COMPUTE_TILE(AB, BB, BIDX)                                            \
    _Pragma("unroll")                                                         \
    for (int ks = 0; ks < 2; ks++) {                                          \
        const int kk = ks * 8;                                                \
        unsigned af[2][4], bf[8][2];                                          \
        _Pragma("unroll")                                                     \
        for (int mf = 0; mf < 2; mf++) {                                      \
            const int r = wm * 32 + mf * 16 + gid;                            \
            af[mf][0] = __float_as_uint(AB[r][kk + tig]);                     \
            af[mf][1] = __float_as_uint(AB[r + 8][kk + tig]);                 \
            af[mf][2] = __float_as_uint(AB[r][kk + tig + 4]);                 \
            af[mf][3] = __float_as_uint(AB[r + 8][kk + tig + 4]);             \
        }                                                                     \
        _Pragma("unroll")                                                     \
        for (int nf = 0; nf < 8; nf++) {                                      \
            const int cb = wn * 64 + nf * 8 + gid;                            \
            bf[nf][0] = BIDX(BB, kk + tig, cb);                               \
            bf[nf][1] = BIDX(BB, kk + tig + 4, cb);                           \
        }                                                                     \
        _Pragma("unroll")                                                     \
        for (int mf = 0; mf < 2; mf++)                                        \
            _Pragma("unroll")                                                 \
            for (int nf = 0; nf < 8; nf++)                                    \
                mma8(acc[mf][nf], af[mf], bf[nf]);                            \
    }

// AV variant: also accumulates per-row sums of A (=E) into rs[2][2].
#define COMPUTE_TILE_AV(AB, BB)                                               \
    _Pragma("unroll")                                                         \
    for (int ks = 0; ks < 2; ks++) {                                          \
        const int kk = ks * 8;                                                \
        float afv[2][4]; unsigned af[2][4], bf[8][2];                         \
        _Pragma("unroll")                                                     \
        for (int mf = 0; mf < 2; mf++) {                                      \
            const int r = wm * 32 + mf * 16 + gid;                            \
            afv[mf][0] = AB[r][kk + tig];                                     \
            afv[mf][1] = AB[r + 8][kk + tig];                                 \
            afv[mf][2] = AB[r][kk + tig + 4];                                 \
            afv[mf][3] = AB[r + 8][kk + tig + 4];                             \
            rs[mf][0] += afv[mf][0] + afv[mf][2];                             \
            rs[mf][1] += afv[mf][1] + afv[mf][3];                             \
            af[mf][0] = __float_as_uint(afv[mf][0]);                          \
            af[mf][1] = __float_as_uint(afv[mf][1]);                          \
            af[mf][2] = __float_as_uint(afv[mf][2]);                          \
            af[mf][3] = __float_as_uint(afv[mf][3]);                          \
        }                                                                     \
        _Pragma("unroll")                                                     \
        for (int nf = 0; nf < 8; nf++) {                                      \
            const int cb = wn * 64 + nf * 8 + gid;                            \
            bf[nf][0] = __float_as_uint(BB[kk + tig][cb]);                    \
            bf[nf][1] = __float_as_uint(BB[kk + tig + 4][cb]);                \
        }                                                                     \
        _Pragma("unroll")                                                     \
        for (int mf = 0; mf < 2; mf++)                                        \
            _Pragma("unroll")                                                 \
            for (int nf = 0; nf < 8; nf++)                                    \
                mma8(acc[mf][nf], af[mf], bf[nf]);                            \
    }

// ---------------------------------------------------------------------------
// Kernel 1: QKV projection.  out[M,512] = X[M,512] @ W[512,512] + bias
// blockIdx.z selects projection (0=Q, 1=K, 2=V).
// ---------------------------------------------------------------------------
__global__ __launch_bounds__(256) void proj_kernel(
    const float* __restrict__ X,
    const float* __restrict__ Wq, const float* __restrict__ bq,
    const float* __restrict__ Wk, const float* __restrict__ bk,
    const float* __restrict__ Wv, const float* __restrict__ bv)
{
    const int which = blockIdx.z;
    const float* W    = (which == 0) ? Wq : (which == 1) ? Wk : Wv;
    const float* bias = (which == 0) ? bq : (which == 1) ? bk : bv;
    float* out        = (which == 0) ? g_q : (which == 1) ? g_k : g_v;

    const int m0 = blockIdx.y * 128;
    const int n0 = blockIdx.x * 128;

    float (*As)[128][20] = (float(*)[128][20])dynsmem;
    float (*Bs)[16][136] = (float(*)[16][136])(dynsmem + 3 * A_STRIDE);

    DECL_TILE_STATE();

    const int ar = tid >> 2, ac = (tid & 3) * 4;      // A: 2 rows (ar, ar+64)
    const int br = tid >> 5, bc = (tid & 31) * 4;     // B: 2 rows (br, br+8)

#define PROJ_ISSUE(s, k0)                                                         \
    do {                                                                          \
        CP16((unsigned)__cvta_generic_to_shared(&As[s][ar][ac]),                  \
             &X[(size_t)(m0 + ar) * 512 + (k0) + ac]);                            \
        CP16((unsigned)__cvta_generic_to_shared(&As[s][ar + 64][ac]),             \
             &X[(size_t)(m0 + ar + 64) * 512 + (k0) + ac]);                       \
        CP16((unsigned)__cvta_generic_to_shared(&Bs[s][br][bc]),                  \
             &W[(size_t)((k0) + br) * 512 + n0 + bc]);                            \
        CP16((unsigned)__cvta_generic_to_shared(&Bs[s][br + 8][bc]),              \
             &W[(size_t)((k0) + br + 8) * 512 + n0 + bc]);                        \
        CPCOMMIT();                                                               \
    } while (0)

    PROJ_ISSUE(0, 0);
    PROJ_ISSUE(1, 16);
    for (int t = 0; t < 32; t++) {
        CPWAIT1();
        __syncthreads();
        if (t + 2 < 32) { const int s = (t + 2) % 3; PROJ_ISSUE(s, (t + 2) * 16); }
        else CPCOMMIT();
        const int cur = t % 3;
        COMPUTE_TILE(As[cur], Bs[cur], BKN);
    }
#undef PROJ_ISSUE

    #pragma unroll
    for (int mf = 0; mf < 2; mf++) {
        const int row = m0 + wm * 32 + mf * 16 + gid;
        #pragma unroll
        for (int nf = 0; nf < 8; nf++) {
            const int col = n0 + wn * 64 + nf * 8 + tig * 2;
            const float b0 = bias[col], b1 = bias[col + 1];
            *(float2*)&out[(size_t)row * 512 + col] =
                make_float2(acc[mf][nf][0] + b0, acc[mf][nf][1] + b1);
            *(float2*)&out[(size_t)(row + 8) * 512 + col] =
                make_float2(acc[mf][nf][2] + b0, acc[mf][nf][3] + b1);
        }
    }
}

// ---------------------------------------------------------------------------
// Kernel 2: copy x into first 512 output channels
// ---------------------------------------------------------------------------
__global__ __launch_bounds__(256) void copy_x_kernel(
    const float4* __restrict__ x4, float4* __restrict__ out4)
{
    const int gid = blockIdx.x * 256 + threadIdx.x;  // MTOT*128 elements
    const int bt = gid >> 7, c4 = gid & 127;
    out4[(size_t)bt * 256 + c4] = x4[gid];
}

// ---------------------------------------------------------------------------
// Kernel 3: E[b,i,j] = exp((q_i.k_j)/sqrt(512)), causal (0 above diagonal).
// No max-subtraction needed: scaled scores are O(1) bounded, exp cannot
// overflow, and normalization is folded into the AV epilogue.
// Lower-triangle tiles only. K tile stays K-major (B frags read as Ks[n][k]).
// ---------------------------------------------------------------------------
__global__ __launch_bounds__(256) void score_kernel()
{
    const int jt = blockIdx.x, it = blockIdx.y, b = blockIdx.z;
    if (jt > it) return;

    const float* q = g_q + (size_t)b * TT * CC;
    const float* k = g_k + (size_t)b * TT * CC;
    float*       S = g_s + (size_t)b * TT * TT;
    const int i0 = it * 128, j0 = jt * 128;

    float (*As)[128][20] = (float(*)[128][20])dynsmem;
    float (*Ks)[128][20] = (float(*)[128][20])(dynsmem + 3 * A_STRIDE);

    DECL_TILE_STATE();

    const int ar = tid >> 2, ac = (tid & 3) * 4;

#define SCORE_ISSUE(s, k0)                                                        \
    do {                                                                          \
        CP16((unsigned)__cvta_generic_to_shared(&As[s][ar][ac]),                  \
             &q[(size_t)(i0 + ar) * 512 + (k0) + ac]);                            \
        CP16((unsigned)__cvta_generic_to_shared(&As[s][ar + 64][ac]),             \
             &q[(size_t)(i0 + ar + 64) * 512 + (k0) + ac]);                       \
        CP16((unsigned)__cvta_generic_to_shared(&Ks[s][ar][ac]),                  \
             &k[(size_t)(j0 + ar) * 512 + (k0) + ac]);                            \
        CP16((unsigned)__cvta_generic_to_shared(&Ks[s][ar + 64][ac]),             \
             &k[(size_t)(j0 + ar + 64) * 512 + (k0) + ac]);                       \
        CPCOMMIT();                                                              \
    } while (0)

    SCORE_ISSUE(0, 0);
    SCORE_ISSUE(1, 16);
    for (int t = 0; t < 32; t++) {
        CPWAIT1();
        __syncthreads();
        if (t + 2 < 32) { const int s = (t + 2) % 3; SCORE_ISSUE(s, (t + 2) * 16); }
        else CPCOMMIT();
        const int cur = t % 3;
        COMPUTE_TILE(As[cur], Ks[cur], BNK);
    }
#undef SCORE_ISSUE

    const float scale = 0.044194173824159216f;  // 1/sqrt(512)
    const bool diag = (it == jt);
    #pragma unroll
    for (int mf = 0; mf < 2; mf++) {
        const int row = i0 + wm * 32 + mf * 16 + gid;
        #pragma unroll
        for (int nf = 0; nf < 8; nf++) {
            const int col = j0 + wn * 64 + nf * 8 + tig * 2;
            float2 o0 = make_float2(__expf(acc[mf][nf][0] * scale),
                                    __expf(acc[mf][nf][1] * scale));
            float2 o1 = make_float2(__expf(acc[mf][nf][2] * scale),
                                    __expf(acc[mf][nf][3] * scale));
            if (diag) {
                if (col     > row)     o0.x = 0.f;
                if (col + 1 > row)     o0.y = 0.f;
                if (col     > row + 8) o1.x = 0.f;
                if (col + 1 > row + 8) o1.y = 0.f;
            }
            *(float2*)&S[(size_t)row * TT + col]       = o0;
            *(float2*)&S[(size_t)(row + 8) * TT + col] = o1;
        }
    }
}

// ---------------------------------------------------------------------------
// Kernel 4: O = (E @ V) / rowsum(E). Row sums come free from A-fragments.
// Causal pairing: block z handles BOTH row-tile z and row-tile 15-z, so every
// block does exactly (z+1 + 16-z) = 17 x 8 = 136 BK-tiles -> uniform runtime,
// no straggler tail (grid 256 blocks, all resident). Writes channels
// [512,1024) of the output.
// ---------------------------------------------------------------------------
__global__ __launch_bounds__(256) void av_kernel(float* __restrict__ out)
{
    const int nt = blockIdx.x, b = blockIdx.y, itz = blockIdx.z;
    const float* P = g_s + (size_t)b * TT * TT;
    const float* v = g_v + (size_t)b * TT * CC;
    const int n0 = nt * 128;

    float (*As)[128][20] = (float(*)[128][20])dynsmem;
    float (*Bs)[16][136] = (float(*)[16][136])(dynsmem + 3 * A_STRIDE);

    DECL_TILE_STATE();

    const int ar = tid >> 2, ac = (tid & 3) * 4;
    const int br = tid >> 5, bc = (tid & 31) * 4;

#define AV_ISSUE(s, k0)                                                           \
    do {                                                                          \
        CP16((unsigned)__cvta_generic_to_shared(&As[s][ar][ac]),                  \
             &P[(size_t)(i0 + ar) * TT + (k0) + ac]);                             \
        CP16((unsigned)__cvta_generic_to_shared(&As[s][ar + 64][ac]),             \
             &P[(size_t)(i0 + ar + 64) * TT + (k0) + ac]);                        \
        CP16((unsigned)__cvta_generic_to_shared(&Bs[s][br][bc]),                  \
             &v[(size_t)((k0) + br) * 512 + n0 + bc]);                            \
        CP16((unsigned)__cvta_generic_to_shared(&Bs[s][br + 8][bc]),              \
             &v[(size_t)((k0) + br + 8) * 512 + n0 + bc]);                        \
        CPCOMMIT();                                                              \
    } while (0)

    for (int ph = 0; ph < 2; ph++) {
        const int it = ph ? 15 - itz : itz;
        const int i0 = it * 128;
        const int nTiles = (it + 1) * 8;   // Kext/16

        float rs[2][2] = {{0.f, 0.f}, {0.f, 0.f}};
        #pragma unroll
        for (int mf = 0; mf < 2; mf++)
            #pragma unroll
            for (int nf = 0; nf < 8; nf++)
                #pragma unroll
                for (int q = 0; q < 4; q++) acc[mf][nf][q] = 0.f;

        // Protect smem ring from the previous phase's in-flight consumers.
        __syncthreads();

        AV_ISSUE(0, 0);
        AV_ISSUE(1, 16);
        for (int t = 0; t < nTiles; t++) {
            CPWAIT1();
            __syncthreads();
            if (t + 2 < nTiles) { const int s = (t + 2) % 3; AV_ISSUE(s, (t + 2) * 16); }
            else CPCOMMIT();
            const int cur = t % 3;
            COMPUTE_TILE_AV(As[cur], Bs[cur]);
        }

        // Reduce row sums across the 4 tig lanes of each nibble.
        #pragma unroll
        for (int mf = 0; mf < 2; mf++)
            #pragma unroll
            for (int j = 0; j < 2; j++) {
                rs[mf][j] += __shfl_xor_sync(~0u, rs[mf][j], 1);
                rs[mf][j] += __shfl_xor_sync(~0u, rs[mf][j], 2);
            }

        #pragma unroll
        for (int mf = 0; mf < 2; mf++) {
            const int row = i0 + wm * 32 + mf * 16 + gid;
            const float inv0 = 1.0f / rs[mf][0];
            const float inv1 = 1.0f / rs[mf][1];
            #pragma unroll
            for (int nf = 0; nf < 8; nf++) {
                const int col = n0 + wn * 64 + nf * 8 + tig * 2;
                const size_t base0 = ((size_t)b * TT + row) * 1024 + 512 + col;
                const size_t base1 = ((size_t)b * TT + row + 8) * 1024 + 512 + col;
                *(float2*)&out[base0] = make_float2(acc[mf][nf][0] * inv0,
                                                    acc[mf][nf][1] * inv0);
                *(float2*)&out[base1] = make_float2(acc[mf][nf][2] * inv1,
                                                    acc[mf][nf][3] * inv1);
            }
        }
    }
#undef AV_ISSUE
}

// ---------------------------------------------------------------------------
extern "C" void kernel_launch(void* const* d_in, const int* in_sizes, int n_in,
                              void* d_out, int out_size)
{
    const float* x  = (const float*)d_in[0];
    const float* Wq = (const float*)d_in[1];
    const float* bq = (const float*)d_in[2];
    const float* Wk = (const float*)d_in[3];
    const float* bk = (const float*)d_in[4];
    const float* Wv = (const float*)d_in[5];
    const float* bv = (const float*)d_in[6];
    float* out = (float*)d_out;

    cudaFuncSetAttribute(proj_kernel,  cudaFuncAttributeMaxDynamicSharedMemorySize, PROJ_SMEM);
    cudaFuncSetAttribute(score_kernel, cudaFuncAttributeMaxDynamicSharedMemorySize, SCORE_SMEM);
    cudaFuncSetAttribute(av_kernel,    cudaFuncAttributeMaxDynamicSharedMemorySize, AV_SMEM);

    proj_kernel<<<dim3(4, 128, 3), 256, PROJ_SMEM>>>(x, Wq, bq, Wk, bk, Wv, bv);

    copy_x_kernel<<<(MTOT * 128) / 256, 256>>>((const float4*)x, (float4*)out);

    score_kernel<<<dim3(16, 16, NB), 256, SCORE_SMEM>>>();
    av_kernel<<<dim3(4, 8, 8), 256, AV_SMEM>>>(out);
}

// round 15
// speedup vs baseline: 1.4764x; 1.4764x over previous
#include <cuda_runtime.h>

// Problem constants
#define NB   8
#define TT   2048
#define CC   512
#define MTOT (NB*TT)        // 16384
#define NPAIR 40            // total (row-tile, K-chunk) pairs for split-K AV

// Scratch (device globals -- no runtime allocation allowed)
__device__ float g_q[MTOT*CC];
__device__ float g_k[MTOT*CC];
__device__ float g_v[MTOT*CC];
__device__ float g_s[(size_t)NB*TT*TT];                 // E = exp(scaled scores)
__device__ float g_par[(size_t)NB*NPAIR*4*128*128];     // split-K partial numerators
__device__ float g_prs[(size_t)NB*NPAIR*128];           // split-K partial row sums

// ---------------------------------------------------------------------------
// mma.sync tf32 (fp32 operands fed raw: HW truncates low mantissa bits)
// ---------------------------------------------------------------------------
__device__ __forceinline__ void mma8(float* c, const unsigned* a, const unsigned* b) {
    asm volatile(
        "mma.sync.aligned.m16n8k8.row.col.f32.tf32.tf32.f32 "
        "{%0,%1,%2,%3}, {%4,%5,%6,%7}, {%8,%9}, {%0,%1,%2,%3};\n"
        : "+f"(c[0]), "+f"(c[1]), "+f"(c[2]), "+f"(c[3])
        : "r"(a[0]), "r"(a[1]), "r"(a[2]), "r"(a[3]), "r"(b[0]), "r"(b[1]));
}

#define CP16(dst, src) \
    asm volatile("cp.async.cg.shared.global [%0], [%1], 16;\n" :: "r"(dst), "l"(src))
#define CPCOMMIT() asm volatile("cp.async.commit_group;\n" ::: "memory")
#define CPWAIT1()  asm volatile("cp.async.wait_group 1;\n" ::: "memory")

// ---------------------------------------------------------------------------
// Tiling: CTA = 128x128, BK = 16, 3-stage cp.async ring (wait_group 1).
// 8 warps in 4(m) x 2(n); warp tile 32x64 = 2 m-frags x 8 n-frags (m16n8k8).
// A tiles: [3][128][20] fp32 (pitch 20 -> conflict-free frag LDS).
// B tiles: KN [3][16][136] (proj/AV) or NK [3][128][20] (score).
// ---------------------------------------------------------------------------
#define A_STRIDE (128*20)
#define B_STRIDE (16*136)
#define PROJ_SMEM  ((3*A_STRIDE + 3*B_STRIDE) * 4)
#define SCORE_SMEM ((3*A_STRIDE * 2) * 4)
#define AV_SMEM    PROJ_SMEM

extern __shared__ float dynsmem[];

#define DECL_TILE_STATE()                                                     \
    const int tid = threadIdx.x;                                              \
    const int wid = tid >> 5, lane = tid & 31;                                \
    const int wm = wid & 3, wn = wid >> 2;                                    \
    const int gid = lane >> 2, tig = lane & 3;                                \
    float acc[2][8][4];                                                       \
    _Pragma("unroll")                                                         \
    for (int mf = 0; mf < 2; mf++)                                            \
        _Pragma("unroll")                                                     \
        for (int nf = 0; nf < 8; nf++)                                        \
            _Pragma("unroll")                                                 \
            for (int q = 0; q < 4; q++) acc[mf][nf][q] = 0.f;

#define BKN(B, k, n) __float_as_uint(B[k][n])
#define BNK(B, k, n) __float_as_uint(B[n][k])

#define COMPUTE_TILE(AB, BB, BIDX)                                            \
    _Pragma("unroll")                                                         \
    for (int ks = 0; ks < 2; ks++) {                                          \
        const int kk = ks * 8;                                                \
        unsigned af[2][4], bf[8][2];                                          \
        _Pragma("unroll")                                                     \
        for (int mf = 0; mf < 2; mf++) {                                      \
            const int r = wm * 32 + mf * 16 + gid;                            \
            af[mf][0] = __float_as_uint(AB[r][kk + tig]);                     \
            af[mf][1] = __float_as_uint(AB[r + 8][kk + tig]);                 \
            af[mf][2] = __float_as_uint(AB[r][kk + tig + 4]);                 \
            af[mf][3] = __float_as_uint(AB[r + 8][kk + tig + 4]);             \
        }                                                                     \
        _Pragma("unroll")                                                     \
        for (int nf = 0; nf < 8; nf++) {                                      \
            const int cb = wn * 64 + nf * 8 + gid;                            \
            bf[nf][0] = BIDX(BB, kk + tig, cb);                               \
            bf[nf][1] = BIDX(BB, kk + tig + 4, cb);                           \
        }                                                                     \
        _Pragma("unroll")                                                     \
        for (int mf = 0; mf < 2; mf++)                                        \
            _Pragma("unroll")                                                 \
            for (int nf = 0; nf < 8; nf++)                                    \
                mma8(acc[mf][nf], af[mf], bf[nf]);                            \
    }

// AV variant: also accumulates per-row sums of A (=E) into rs[2][2].
#define COMPUTE_TILE_AV(AB, BB)                                               \
    _Pragma("unroll")                                                         \
    for (int ks = 0; ks < 2; ks++) {                                          \
        const int kk = ks * 8;                                                \
        float afv[2][4]; unsigned af[2][4], bf[8][2];                         \
        _Pragma("unroll")                                                     \
        for (int mf = 0; mf < 2; mf++) {                                      \
            const int r = wm * 32 + mf * 16 + gid;                            \
            afv[mf][0] = AB[r][kk + tig];                                     \
            afv[mf][1] = AB[r + 8][kk + tig];                                 \
            afv[mf][2] = AB[r][kk + tig + 4];                                 \
            afv[mf][3] = AB[r + 8][kk + tig + 4];                             \
            rs[mf][0] += afv[mf][0] + afv[mf][2];                             \
            rs[mf][1] += afv[mf][1] + afv[mf][3];                             \
            af[mf][0] = __float_as_uint(afv[mf][0]);                          \
            af[mf][1] = __float_as_uint(afv[mf][1]);                          \
            af[mf][2] = __float_as_uint(afv[mf][2]);                          \
            af[mf][3] = __float_as_uint(afv[mf][3]);                          \
        }                                                                     \
        _Pragma("unroll")                                                     \
        for (int nf = 0; nf < 8; nf++) {                                      \
            const int cb = wn * 64 + nf * 8 + gid;                            \
            bf[nf][0] = __float_as_uint(BB[kk + tig][cb]);                    \
            bf[nf][1] = __float_as_uint(BB[kk + tig + 4][cb]);                \
        }                                                                     \
        _Pragma("unroll")                                                     \
        for (int mf = 0; mf < 2; mf++)                                        \
            _Pragma("unroll")                                                 \
            for (int nf = 0; nf < 8; nf++)                                    \
                mma8(acc[mf][nf], af[mf], bf[nf]);                            \
    }

// ---------------------------------------------------------------------------
// Kernel 1: QKV projection.  out[M,512] = X[M,512] @ W[512,512] + bias
// ---------------------------------------------------------------------------
__global__ __launch_bounds__(256) void proj_kernel(
    const float* __restrict__ X,
    const float* __restrict__ Wq, const float* __restrict__ bq,
    const float* __restrict__ Wk, const float* __restrict__ bk,
    const float* __restrict__ Wv, const float* __restrict__ bv)
{
    const int which = blockIdx.z;
    const float* W    = (which == 0) ? Wq : (which == 1) ? Wk : Wv;
    const float* bias = (which == 0) ? bq : (which == 1) ? bk : bv;
    float* out        = (which == 0) ? g_q : (which == 1) ? g_k : g_v;

    const int m0 = blockIdx.y * 128;
    const int n0 = blockIdx.x * 128;

    float (*As)[128][20] = (float(*)[128][20])dynsmem;
    float (*Bs)[16][136] = (float(*)[16][136])(dynsmem + 3 * A_STRIDE);

    DECL_TILE_STATE();

    const int ar = tid >> 2, ac = (tid & 3) * 4;      // A: 2 rows (ar, ar+64)
    const int br = tid >> 5, bc = (tid & 31) * 4;     // B: 2 rows (br, br+8)

#define PROJ_ISSUE(s, k0)                                                         \
    do {                                                                          \
        CP16((unsigned)__cvta_generic_to_shared(&As[s][ar][ac]),                  \
             &X[(size_t)(m0 + ar) * 512 + (k0) + ac]);                            \
        CP16((unsigned)__cvta_generic_to_shared(&As[s][ar + 64][ac]),             \
             &X[(size_t)(m0 + ar + 64) * 512 + (k0) + ac]);                       \
        CP16((unsigned)__cvta_generic_to_shared(&Bs[s][br][bc]),                  \
             &W[(size_t)((k0) + br) * 512 + n0 + bc]);                            \
        CP16((unsigned)__cvta_generic_to_shared(&Bs[s][br + 8][bc]),              \
             &W[(size_t)((k0) + br + 8) * 512 + n0 + bc]);                        \
        CPCOMMIT();                                                               \
    } while (0)

    PROJ_ISSUE(0, 0);
    PROJ_ISSUE(1, 16);
    for (int t = 0; t < 32; t++) {
        CPWAIT1();
        __syncthreads();
        if (t + 2 < 32) { const int s = (t + 2) % 3; PROJ_ISSUE(s, (t + 2) * 16); }
        else CPCOMMIT();
        const int cur = t % 3;
        COMPUTE_TILE(As[cur], Bs[cur], BKN);
    }
#undef PROJ_ISSUE

    #pragma unroll
    for (int mf = 0; mf < 2; mf++) {
        const int row = m0 + wm * 32 + mf * 16 + gid;
        #pragma unroll
        for (int nf = 0; nf < 8; nf++) {
            const int col = n0 + wn * 64 + nf * 8 + tig * 2;
            const float b0 = bias[col], b1 = bias[col + 1];
            *(float2*)&out[(size_t)row * 512 + col] =
                make_float2(acc[mf][nf][0] + b0, acc[mf][nf][1] + b1);
            *(float2*)&out[(size_t)(row + 8) * 512 + col] =
                make_float2(acc[mf][nf][2] + b0, acc[mf][nf][3] + b1);
        }
    }
}

// ---------------------------------------------------------------------------
// Kernel 2: copy x into first 512 output channels
// ---------------------------------------------------------------------------
__global__ __launch_bounds__(256) void copy_x_kernel(
    const float4* __restrict__ x4, float4* __restrict__ out4)
{
    const int gid = blockIdx.x * 256 + threadIdx.x;  // MTOT*128 elements
    const int bt = gid >> 7, c4 = gid & 127;
    out4[(size_t)bt * 256 + c4] = x4[gid];
}

// ---------------------------------------------------------------------------
// Kernel 3: E[b,i,j] = exp((q_i.k_j)/sqrt(512)), causal (0 above diagonal).
// Normalization deferred to the AV reduce. Lower-triangle tiles only.
// ---------------------------------------------------------------------------
__global__ __launch_bounds__(256) void score_kernel()
{
    const int jt = blockIdx.x, it = blockIdx.y, b = blockIdx.z;
    if (jt > it) return;

    const float* q = g_q + (size_t)b * TT * CC;
    const float* k = g_k + (size_t)b * TT * CC;
    float*       S = g_s + (size_t)b * TT * TT;
    const int i0 = it * 128, j0 = jt * 128;

    float (*As)[128][20] = (float(*)[128][20])dynsmem;
    float (*Ks)[128][20] = (float(*)[128][20])(dynsmem + 3 * A_STRIDE);

    DECL_TILE_STATE();

    const int ar = tid >> 2, ac = (tid & 3) * 4;

#define SCORE_ISSUE(s, k0)                                                        \
    do {                                                                          \
        CP16((unsigned)__cvta_generic_to_shared(&As[s][ar][ac]),                  \
             &q[(size_t)(i0 + ar) * 512 + (k0) + ac]);                            \
        CP16((unsigned)__cvta_generic_to_shared(&As[s][ar + 64][ac]),             \
             &q[(size_t)(i0 + ar + 64) * 512 + (k0) + ac]);                       \
        CP16((unsigned)__cvta_generic_to_shared(&Ks[s][ar][ac]),                  \
             &k[(size_t)(j0 + ar) * 512 + (k0) + ac]);                            \
        CP16((unsigned)__cvta_generic_to_shared(&Ks[s][ar + 64][ac]),             \
             &k[(size_t)(j0 + ar + 64) * 512 + (k0) + ac]);                       \
        CPCOMMIT();                                                              \
    } while (0)

    SCORE_ISSUE(0, 0);
    SCORE_ISSUE(1, 16);
    for (int t = 0; t < 32; t++) {
        CPWAIT1();
        __syncthreads();
        if (t + 2 < 32) { const int s = (t + 2) % 3; SCORE_ISSUE(s, (t + 2) * 16); }
        else CPCOMMIT();
        const int cur = t % 3;
        COMPUTE_TILE(As[cur], Ks[cur], BNK);
    }
#undef SCORE_ISSUE

    const float scale = 0.044194173824159216f;  // 1/sqrt(512)
    const bool diag = (it == jt);
    #pragma unroll
    for (int mf = 0; mf < 2; mf++) {
        const int row = i0 + wm * 32 + mf * 16 + gid;
        #pragma unroll
        for (int nf = 0; nf < 8; nf++) {
            const int col = j0 + wn * 64 + nf * 8 + tig * 2;
            float2 o0 = make_float2(__expf(acc[mf][nf][0] * scale),
                                    __expf(acc[mf][nf][1] * scale));
            float2 o1 = make_float2(__expf(acc[mf][nf][2] * scale),
                                    __expf(acc[mf][nf][3] * scale));
            if (diag) {
                if (col     > row)     o0.x = 0.f;
                if (col + 1 > row)     o0.y = 0.f;
                if (col     > row + 8) o1.x = 0.f;
                if (col + 1 > row + 8) o1.y = 0.f;
            }
            *(float2*)&S[(size_t)row * TT + col]       = o0;
            *(float2*)&S[(size_t)(row + 8) * TT + col] = o1;
        }
    }
}

// ---------------------------------------------------------------------------
// Kernel 4a: split-K AV partials. Pair p in [0,40) decodes to (it, c): row-tile
// it with K-chunk c covering K rows [c*512, min((it+1)*128, c*512+512)).
// Critical path <= 32 BK-tiles (vs 128 unsplit). Writes unnormalized partial
// numerator tile [128x128] and partial row sums [128] to scratch.
// ---------------------------------------------------------------------------
__global__ __launch_bounds__(256) void av_chunk_kernel()
{
    const int nt = blockIdx.x, p = blockIdx.y, b = blockIdx.z;
    int it, c;
    if (p < 4)       { it = p;                c = 0;          }
    else if (p < 12) { it = 4 + (p - 4) / 2;  c = (p - 4) % 2; }
    else if (p < 24) { it = 8 + (p - 12) / 3; c = (p - 12) % 3; }
    else             { it = 12 + (p - 24) / 4; c = (p - 24) % 4; }

    const float* P = g_s + (size_t)b * TT * TT;
    const float* v = g_v + (size_t)b * TT * CC;
    const int i0 = it * 128, n0 = nt * 128;
    const int kbase = c * 512;
    const int nTiles = min(32, (it + 1) * 8 - c * 32);   // >= 8

    float (*As)[128][20] = (float(*)[128][20])dynsmem;
    float (*Bs)[16][136] = (float(*)[16][136])(dynsmem + 3 * A_STRIDE);

    DECL_TILE_STATE();

    float rs[2][2] = {{0.f, 0.f}, {0.f, 0.f}};

    const int ar = tid >> 2, ac = (tid & 3) * 4;
    const int br = tid >> 5, bc = (tid & 31) * 4;

#define AV_ISSUE(s, k0)                                                           \
    do {                                                                          \
        CP16((unsigned)__cvta_generic_to_shared(&As[s][ar][ac]),                  \
             &P[(size_t)(i0 + ar) * TT + kbase + (k0) + ac]);                     \
        CP16((unsigned)__cvta_generic_to_shared(&As[s][ar + 64][ac]),             \
             &P[(size_t)(i0 + ar + 64) * TT + kbase + (k0) + ac]);                \
        CP16((unsigned)__cvta_generic_to_shared(&Bs[s][br][bc]),                  \
             &v[(size_t)(kbase + (k0) + br) * 512 + n0 + bc]);                    \
        CP16((unsigned)__cvta_generic_to_shared(&Bs[s][br + 8][bc]),              \
             &v[(size_t)(kbase + (k0) + br + 8) * 512 + n0 + bc]);                \
        CPCOMMIT();                                                               \
    } while (0)

    AV_ISSUE(0, 0);
    AV_ISSUE(1, 16);
    for (int t = 0; t < nTiles; t++) {
        CPWAIT1();
        __syncthreads();
        if (t + 2 < nTiles) { const int s = (t + 2) % 3; AV_ISSUE(s, (t + 2) * 16); }
        else CPCOMMIT();
        const int cur = t % 3;
        COMPUTE_TILE_AV(As[cur], Bs[cur]);
    }
#undef AV_ISSUE

    // Reduce row sums across the 4 tig lanes of each nibble.
    #pragma unroll
    for (int mf = 0; mf < 2; mf++)
        #pragma unroll
        for (int j = 0; j < 2; j++) {
            rs[mf][j] += __shfl_xor_sync(~0u, rs[mf][j], 1);
            rs[mf][j] += __shfl_xor_sync(~0u, rs[mf][j], 2);
        }

    float* par = g_par + (((size_t)b * NPAIR + p) * 4 + nt) * (128 * 128);
    float* prs = g_prs + ((size_t)b * NPAIR + p) * 128;

    #pragma unroll
    for (int mf = 0; mf < 2; mf++) {
        const int rl = wm * 32 + mf * 16 + gid;      // local row 0..127
        if (wn == 0 && tig == 0) {
            prs[rl]     = rs[mf][0];
            prs[rl + 8] = rs[mf][1];
        }
        #pragma unroll
        for (int nf = 0; nf < 8; nf++) {
            const int cl = wn * 64 + nf * 8 + tig * 2;  // local col
            *(float2*)&par[(size_t)rl * 128 + cl] =
                make_float2(acc[mf][nf][0], acc[mf][nf][1]);
            *(float2*)&par[(size_t)(rl + 8) * 128 + cl] =
                make_float2(acc[mf][nf][2], acc[mf][nf][3]);
        }
    }
}

// ---------------------------------------------------------------------------
// Kernel 4b: combine split-K partials: O = (sum_c par_c) / (sum_c prs_c).
// Pairs for row-tile it are contiguous: start = 2g(g+1) + (it&3)(g+1), g=it/4.
// Writes channels [512,1024) of the output.
// ---------------------------------------------------------------------------
__global__ __launch_bounds__(256) void av_reduce_kernel(float* __restrict__ out)
{
    const int nt = blockIdx.x, it = blockIdx.y, b = blockIdx.z;
    const int g = it >> 2, nc = g + 1;
    const int start = 2 * g * (g + 1) + (it & 3) * nc;
    const int tid = threadIdx.x;

    __shared__ float rinv[128];
    if (tid < 128) {
        float s = 0.f;
        for (int pp = 0; pp < nc; pp++)
            s += g_prs[((size_t)b * NPAIR + start + pp) * 128 + tid];
        rinv[tid] = 1.0f / s;
    }
    __syncthreads();

    const int i0 = it * 128, n0 = nt * 128;
    const float4* pbase = (const float4*)(g_par);
    // element-4 index within the 128x128 tile: 4096 float4s
    for (int e = tid; e < 4096; e += 256) {
        float4 s = make_float4(0.f, 0.f, 0.f, 0.f);
        for (int pp = 0; pp < nc; pp++) {
            const float4 v = pbase[(((size_t)b * NPAIR + start + pp) * 4 + nt) * 4096 + e];
            s.x += v.x; s.y += v.y; s.z += v.z; s.w += v.w;
        }
        const int row = e >> 5, col4 = (e & 31) * 4;    // 32 float4s per row
        const float inv = rinv[row];
        s.x *= inv; s.y *= inv; s.z *= inv; s.w *= inv;
        *(float4*)&out[((size_t)b * TT + i0 + row) * 1024 + 512 + n0 + col4] = s;
    }
}

// ---------------------------------------------------------------------------
extern "C" void kernel_launch(void* const* d_in, const int* in_sizes, int n_in,
                              void* d_out, int out_size)
{
    const float* x  = (const float*)d_in[0];
    const float* Wq = (const float*)d_in[1];
    const float* bq = (const float*)d_in[2];
    const float* Wk = (const float*)d_in[3];
    const float* bk = (const float*)d_in[4];
    const float* Wv = (const float*)d_in[5];
    const float* bv = (const float*)d_in[6];
    float* out = (float*)d_out;

    cudaFuncSetAttribute(proj_kernel,     cudaFuncAttributeMaxDynamicSharedMemorySize, PROJ_SMEM);
    cudaFuncSetAttribute(score_kernel,    cudaFuncAttributeMaxDynamicSharedMemorySize, SCORE_SMEM);
    cudaFuncSetAttribute(av_chunk_kernel, cudaFuncAttributeMaxDynamicSharedMemorySize, AV_SMEM);

    proj_kernel<<<dim3(4, 128, 3), 256, PROJ_SMEM>>>(x, Wq, bq, Wk, bk, Wv, bv);

    copy_x_kernel<<<(MTOT * 128) / 256, 256>>>((const float4*)x, (float4*)out);

    score_kernel<<<dim3(16, 16, NB), 256, SCORE_SMEM>>>();
    av_chunk_kernel<<<dim3(4, NPAIR, NB), 256, AV_SMEM>>>();
    av_reduce_kernel<<<dim3(4, 16, NB), 256>>>(out);
}

// round 17
// speedup vs baseline: 2.0061x; 1.3588x over previous
#include <cuda_runtime.h>
#include <cuda_fp16.h>
#include <cstdint>

// Problem constants
#define NB   8
#define TT   2048
#define CC   512
#define MTOT (NB*TT)        // 16384
#define NPAIR 40            // (row-tile, K-chunk) pairs for split-K AV

// Scratch (device globals -- no runtime allocation allowed)
__device__ __half g_xh[(size_t)MTOT*CC];         // x in fp16 (row-major = K-major)
__device__ __half g_wth[3][CC*CC];               // W^T in fp16: [n][k]
__device__ __half g_qh[(size_t)MTOT*CC];
__device__ __half g_kh[(size_t)MTOT*CC];
__device__ __half g_vh[(size_t)MTOT*CC];
__device__ __half g_vth[(size_t)NB*CC*TT];       // V^T per batch: [c][t]
__device__ __half g_sh[(size_t)NB*TT*TT];        // E = exp(scaled scores), fp16
__device__ float  g_par[(size_t)NB*NPAIR*4*128*128]; // split-K partial numerators
__device__ float  g_prs[(size_t)NB*NPAIR*128];       // split-K partial row sums

// ---------------------------------------------------------------------------
// mma.sync fp16 m16n8k16, fp32 accumulate
// ---------------------------------------------------------------------------
__device__ __forceinline__ void mma16(float* c, const unsigned* a, const unsigned* b) {
    asm volatile(
        "mma.sync.aligned.m16n8k16.row.col.f32.f16.f16.f32 "
        "{%0,%1,%2,%3}, {%4,%5,%6,%7}, {%8,%9}, {%0,%1,%2,%3};\n"
        : "+f"(c[0]), "+f"(c[1]), "+f"(c[2]), "+f"(c[3])
        : "r"(a[0]), "r"(a[1]), "r"(a[2]), "r"(a[3]), "r"(b[0]), "r"(b[1]));
}

#define CP16(dst, src) \
    asm volatile("cp.async.cg.shared.global [%0], [%1], 16;\n" :: "r"(dst), "l"(src))
#define CPCOMMIT() asm volatile("cp.async.commit_group;\n" ::: "memory")
#define CPWAIT1()  asm volatile("cp.async.wait_group 1;\n" ::: "memory")

__device__ __forceinline__ uint32_t sm_u32(const void* p) {
    uint32_t a;
    asm("{ .reg .u64 t; cvta.to.shared.u64 t, %1; cvt.u32.u64 %0, t; }"
        : "=r"(a) : "l"(p));
    return a;
}

// ---------------------------------------------------------------------------
// Tiling: CTA 128x128, BK = 32 fp16 (64B rows), 3-stage cp.async ring.
// 8 warps in 4(m) x 2(n); warp tile 32x64 = 2 m-frags x 8 n-frags (m16n8k16).
// BOTH operands K-major [128 rows][32 k] fp16, stored as uint32 half2 words,
// row pitch 20 words (16 data + 4 pad -> (gid*20+tig) mod 32 all distinct =
// conflict-free fragment LDS). Every fragment register is one 32-bit LDS.
// ---------------------------------------------------------------------------
#define TILE_W 20
#define STGW  (128*TILE_W)                 // 2560 words per stage
#define GSMEM (6*STGW*4)                   // 61440 bytes (3 A + 3 B stages)
extern __shared__ uint32_t dynu[];

#define DECL_TILE_STATE()                                                     \
    const int tid = threadIdx.x;                                              \
    const int wid = tid >> 5, lane = tid & 31;                                \
    const int wm = wid & 3, wn = wid >> 2;                                    \
    const int gid = lane >> 2, tig = lane & 3;                                \
    float acc[2][8][4];                                                       \
    _Pragma("unroll")                                                         \
    for (int mf = 0; mf < 2; mf++)                                            \
        _Pragma("unroll")                                                     \
        for (int nf = 0; nf < 8; nf++)                                        \
            _Pragma("unroll")                                                 \
            for (int q = 0; q < 4; q++) acc[mf][nf][q] = 0.f;

// Per BK=32 tile: 2 k16 slices; per slice 8 A-LDS + 16 B-LDS feed 16 mma16.
#define COMPUTE16(SA, SB)                                                     \
    _Pragma("unroll")                                                         \
    for (int ks = 0; ks < 2; ks++) {                                          \
        const int kw = ks * 8;                                                \
        unsigned af[2][4], bf[8][2];                                          \
        _Pragma("unroll")                                                     \
        for (int mf = 0; mf < 2; mf++) {                                      \
            const int r = wm * 32 + mf * 16 + gid;                            \
            af[mf][0] = SA[r * TILE_W + kw + tig];                            \
            af[mf][1] = SA[(r + 8) * TILE_W + kw + tig];                      \
            af[mf][2] = SA[r * TILE_W + kw + tig + 4];                        \
            af[mf][3] = SA[(r + 8) * TILE_W + kw + tig + 4];                  \
        }                                                                     \
        _Pragma("unroll")                                                     \
        for (int nf = 0; nf < 8; nf++) {                                      \
            const int cb = wn * 64 + nf * 8 + gid;                            \
            bf[nf][0] = SB[cb * TILE_W + kw + tig];                           \
            bf[nf][1] = SB[cb * TILE_W + kw + tig + 4];                       \
        }                                                                     \
        _Pragma("unroll")                                                     \
        for (int mf = 0; mf < 2; mf++)                                        \
            _Pragma("unroll")                                                 \
            for (int nf = 0; nf < 8; nf++)                                    \
                mma16(acc[mf][nf], af[mf], bf[nf]);                           \
    }

// AV variant: also accumulates per-row sums of A (=E). a0/a2 belong to row r,
// a1/a3 to row r+8; tig quad covers k 0..15 exactly once -> shfl-reduce later.
#define COMPUTE16_AV(SA, SB)                                                  \
    _Pragma("unroll")                                                         \
    for (int ks = 0; ks < 2; ks++) {                                          \
        const int kw = ks * 8;                                                \
        unsigned af[2][4], bf[8][2];                                          \
        _Pragma("unroll")                                                     \
        for (int mf = 0; mf < 2; mf++) {                                      \
            const int r = wm * 32 + mf * 16 + gid;                            \
            af[mf][0] = SA[r * TILE_W + kw + tig];                            \
            af[mf][1] = SA[(r + 8) * TILE_W + kw + tig];                      \
            af[mf][2] = SA[r * TILE_W + kw + tig + 4];                        \
            af[mf][3] = SA[(r + 8) * TILE_W + kw + tig + 4];                  \
            float2 f;                                                         \
            f = __half22float2(*(__half2*)&af[mf][0]); rs[mf][0] += f.x + f.y;\
            f = __half22float2(*(__half2*)&af[mf][2]); rs[mf][0] += f.x + f.y;\
            f = __half22float2(*(__half2*)&af[mf][1]); rs[mf][1] += f.x + f.y;\
            f = __half22float2(*(__half2*)&af[mf][3]); rs[mf][1] += f.x + f.y;\
        }                                                                     \
        _Pragma("unroll")                                                     \
        for (int nf = 0; nf < 8; nf++) {                                      \
            const int cb = wn * 64 + nf * 8 + gid;                            \
            bf[nf][0] = SB[cb * TILE_W + kw + tig];                           \
            bf[nf][1] = SB[cb * TILE_W + kw + tig + 4];                       \
        }                                                                     \
        _Pragma("unroll")                                                     \
        for (int mf = 0; mf < 2; mf++)                                        \
            _Pragma("unroll")                                                 \
            for (int nf = 0; nf < 8; nf++)                                    \
                mma16(acc[mf][nf], af[mf], bf[nf]);                           \
    }

// Generic loader: each thread loads 2x16B per matrix (row lr, 32B half-row).
#define DECL_LOADER(Arow, lda, Brow, ldb)                                     \
    const int lr = tid >> 1;                                                  \
    const unsigned dstb = (lr * TILE_W + (tid & 1) * 8) * 4;                  \
    const __half* aS = (Arow) + (size_t)lr * (lda) + (tid & 1) * 16;          \
    const __half* bS = (Brow) + (size_t)lr * (ldb) + (tid & 1) * 16;          \
    const uint32_t smb = sm_u32(dynu);                                        \
    const uint32_t uA[3] = {smb, smb + STGW*4, smb + 2*STGW*4};               \
    const uint32_t uB[3] = {smb + 3*STGW*4, smb + 4*STGW*4, smb + 5*STGW*4};

#define GISSUE(s, k0)                                                         \
    do {                                                                      \
        CP16(uA[s] + dstb,      aS + (k0));                                   \
        CP16(uA[s] + dstb + 16, aS + (k0) + 8);                               \
        CP16(uB[s] + dstb,      bS + (k0));                                   \
        CP16(uB[s] + dstb + 16, bS + (k0) + 8);                               \
        CPCOMMIT();                                                           \
    } while (0)

#define MAINLOOP(nT, CMP)                                                     \
    GISSUE(0, 0);                                                             \
    GISSUE(1, 32);                                                            \
    for (int t = 0; t < (nT); t++) {                                          \
        CPWAIT1();                                                            \
        __syncthreads();                                                      \
        if (t + 2 < (nT)) { const int s = (t + 2) % 3; GISSUE(s, (t + 2) * 32); } \
        else CPCOMMIT();                                                      \
        const uint32_t* SA = dynu + (t % 3) * STGW;                           \
        const uint32_t* SB = dynu + (3 + t % 3) * STGW;                       \
        CMP(SA, SB);                                                          \
    }

// ---------------------------------------------------------------------------
// Kernel 1: convert x -> fp16
// ---------------------------------------------------------------------------
__global__ __launch_bounds__(256) void x2h_kernel(const float4* __restrict__ x4)
{
    const int gid = blockIdx.x * 256 + threadIdx.x;   // MTOT*CC/4 elements
    const float4 v = x4[gid];
    const __half2 h0 = __floats2half2_rn(v.x, v.y);
    const __half2 h1 = __floats2half2_rn(v.z, v.w);
    uint2 o;
    o.x = *(const uint32_t*)&h0;
    o.y = *(const uint32_t*)&h1;
    *(uint2*)&g_xh[(size_t)gid * 4] = o;
}

// ---------------------------------------------------------------------------
// Kernel 2: W transpose+convert  g_wth[which][n][k] = half(W[k][n])
// ---------------------------------------------------------------------------
__global__ __launch_bounds__(256) void wt_kernel(
    const float* __restrict__ Wq, const float* __restrict__ Wk,
    const float* __restrict__ Wv)
{
    const int which = blockIdx.z;
    const float* W = (which == 0) ? Wq : (which == 1) ? Wk : Wv;
    __shared__ float tile[32][33];
    const int k0 = blockIdx.x * 32, n0 = blockIdx.y * 32;
    const int tx = threadIdx.x & 31, ty = threadIdx.x >> 5;
    #pragma unroll
    for (int j = 0; j < 4; j++)
        tile[ty + 8 * j][tx] = W[(size_t)(k0 + ty + 8 * j) * CC + n0 + tx];
    __syncthreads();
    #pragma unroll
    for (int j = 0; j < 4; j++)
        g_wth[which][(size_t)(n0 + ty + 8 * j) * CC + k0 + tx] =
            __float2half(tile[tx][ty + 8 * j]);
}

// ---------------------------------------------------------------------------
// Kernel 3: QKV projection (fp16 MMA).  out[M,512] = X @ W + b, fp16 out.
// ---------------------------------------------------------------------------
__global__ __launch_bounds__(256) void proj_kernel(
    const float* __restrict__ bq, const float* __restrict__ bk,
    const float* __restrict__ bv)
{
    const int which = blockIdx.z;
    const float* bias = (which == 0) ? bq : (which == 1) ? bk : bv;
    __half* out      = (which == 0) ? g_qh : (which == 1) ? g_kh : g_vh;
    const int m0 = blockIdx.y * 128, n0 = blockIdx.x * 128;

    DECL_TILE_STATE();
    DECL_LOADER(g_xh + (size_t)m0 * CC, CC, g_wth[which] + (size_t)n0 * CC, CC);
    MAINLOOP(16, COMPUTE16);

    #pragma unroll
    for (int mf = 0; mf < 2; mf++) {
        const int row = m0 + wm * 32 + mf * 16 + gid;
        #pragma unroll
        for (int nf = 0; nf < 8; nf++) {
            const int col = n0 + wn * 64 + nf * 8 + tig * 2;
            const float b0 = bias[col], b1 = bias[col + 1];
            const __half2 h0 = __floats2half2_rn(acc[mf][nf][0] + b0,
                                                 acc[mf][nf][1] + b1);
            const __half2 h1 = __floats2half2_rn(acc[mf][nf][2] + b0,
                                                 acc[mf][nf][3] + b1);
            *(uint32_t*)&out[(size_t)row * CC + col]       = *(const uint32_t*)&h0;
            *(uint32_t*)&out[(size_t)(row + 8) * CC + col] = *(const uint32_t*)&h1;
        }
    }
}

// ---------------------------------------------------------------------------
// Kernel 4: copy x into first 512 output channels (fp32)
// ---------------------------------------------------------------------------
__global__ __launch_bounds__(256) void copy_x_kernel(
    const float4* __restrict__ x4, float4* __restrict__ out4)
{
    const int gid = blockIdx.x * 256 + threadIdx.x;
    const int bt = gid >> 7, c4 = gid & 127;
    out4[(size_t)bt * 256 + c4] = x4[gid];
}

// ---------------------------------------------------------------------------
// Kernel 5: V transpose per batch (fp16): g_vth[b][c][t] = g_vh[b*T+t][c]
// 64(t) x 64(c) tiles via packed half2 words.
// ---------------------------------------------------------------------------
__global__ __launch_bounds__(256) void vt_kernel()
{
    const int b = blockIdx.z, t0 = blockIdx.x * 64, c0 = blockIdx.y * 64;
    __shared__ uint32_t sm[64][33];
    const int tx = threadIdx.x & 31, ty = threadIdx.x >> 5;
    #pragma unroll
    for (int i = 0; i < 8; i++) {
        const int t = ty + 8 * i;
        sm[t][tx] = *(const uint32_t*)&g_vh[((size_t)b * TT + t0 + t) * CC + c0 + tx * 2];
    }
    __syncthreads();
    #pragma unroll
    for (int i = 0; i < 8; i++) {
        const int cc = ty + 8 * i;
        const uint32_t w0 = sm[2 * tx][cc >> 1];
        const uint32_t w1 = sm[2 * tx + 1][cc >> 1];
        const __half h0 = ((const __half*)&w0)[cc & 1];
        const __half h1 = ((const __half*)&w1)[cc & 1];
        const __half2 o = __halves2half2(h0, h1);
        *(uint32_t*)&g_vth[((size_t)b * CC + c0 + cc) * TT + t0 + 2 * tx] =
            *(const uint32_t*)&o;
    }
}

// ---------------------------------------------------------------------------
// Kernel 6: E = exp((Q.K^T)/sqrt(512)) fp16, causal zeros; lower tiles only.
// ---------------------------------------------------------------------------
__global__ __launch_bounds__(256) void score_kernel()
{
    const int jt = blockIdx.x, it = blockIdx.y, b = blockIdx.z;
    if (jt > it) return;
    const int i0 = it * 128, j0 = jt * 128;

    DECL_TILE_STATE();
    DECL_LOADER(g_qh + ((size_t)b * TT + i0) * CC, CC,
                g_kh + ((size_t)b * TT + j0) * CC, CC);
    MAINLOOP(16, COMPUTE16);

    const float scale = 0.044194173824159216f;  // 1/sqrt(512)
    const bool diag = (it == jt);
    __half* S = g_sh + (size_t)b * TT * TT;
    #pragma unroll
    for (int mf = 0; mf < 2; mf++) {
        const int row = i0 + wm * 32 + mf * 16 + gid;
        #pragma unroll
        for (int nf = 0; nf < 8; nf++) {
            const int col = j0 + wn * 64 + nf * 8 + tig * 2;
            float e0 = __expf(acc[mf][nf][0] * scale);
            float e1 = __expf(acc[mf][nf][1] * scale);
            float e2 = __expf(acc[mf][nf][2] * scale);
            float e3 = __expf(acc[mf][nf][3] * scale);
            if (diag) {
                if (col     > row)     e0 = 0.f;
                if (col + 1 > row)     e1 = 0.f;
                if (col     > row + 8) e2 = 0.f;
                if (col + 1 > row + 8) e3 = 0.f;
            }
            const __half2 h0 = __floats2half2_rn(e0, e1);
            const __half2 h1 = __floats2half2_rn(e2, e3);
            *(uint32_t*)&S[(size_t)row * TT + col]       = *(const uint32_t*)&h0;
            *(uint32_t*)&S[(size_t)(row + 8) * TT + col] = *(const uint32_t*)&h1;
        }
    }
}

// ---------------------------------------------------------------------------
// Kernel 7: split-K AV partials (fp16 MMA). Pair p -> (it, c): K rows
// [c*512, min((it+1)*128, c*512+512)). Row sums from the quantized A-frags
// (consistent with the numerator). fp32 partials to scratch.
// ---------------------------------------------------------------------------
__global__ __launch_bounds__(256) void av_chunk_kernel()
{
    const int nt = blockIdx.x, p = blockIdx.y, b = blockIdx.z;
    int it, c;
    if (p < 4)       { it = p;                 c = 0;            }
    else if (p < 12) { it = 4 + (p - 4) / 2;   c = (p - 4) % 2;  }
    else if (p < 24) { it = 8 + (p - 12) / 3;  c = (p - 12) % 3; }
    else             { it = 12 + (p - 24) / 4; c = (p - 24) % 4; }

    const int i0 = it * 128, n0 = nt * 128;
    const int kbase = c * 512;
    const int nT = min(16, (it + 1) * 4 - c * 16);   // BK=32 tiles, >= 4

    float rs[2][2] = {{0.f, 0.f}, {0.f, 0.f}};

    DECL_TILE_STATE();
    DECL_LOADER(g_sh + (size_t)b * TT * TT + (size_t)i0 * TT + kbase, TT,
                g_vth + ((size_t)b * CC + n0) * TT + kbase, TT);
    MAINLOOP(nT, COMPUTE16_AV);

    #pragma unroll
    for (int mf = 0; mf < 2; mf++)
        #pragma unroll
        for (int j = 0; j < 2; j++) {
            rs[mf][j] += __shfl_xor_sync(~0u, rs[mf][j], 1);
            rs[mf][j] += __shfl_xor_sync(~0u, rs[mf][j], 2);
        }

    float* par = g_par + (((size_t)b * NPAIR + p) * 4 + nt) * (128 * 128);
    float* prs = g_prs + ((size_t)b * NPAIR + p) * 128;

    #pragma unroll
    for (int mf = 0; mf < 2; mf++) {
        const int rl = wm * 32 + mf * 16 + gid;
        if (wn == 0 && tig == 0) {
            prs[rl]     = rs[mf][0];
            prs[rl + 8] = rs[mf][1];
        }
        #pragma unroll
        for (int nf = 0; nf < 8; nf++) {
            const int cl = wn * 64 + nf * 8 + tig * 2;
            *(float2*)&par[(size_t)rl * 128 + cl] =
                make_float2(acc[mf][nf][0], acc[mf][nf][1]);
            *(float2*)&par[(size_t)(rl + 8) * 128 + cl] =
                make_float2(acc[mf][nf][2], acc[mf][nf][3]);
        }
    }
}

// ---------------------------------------------------------------------------
// Kernel 8: combine split-K partials: O = (sum par) / (sum prs).
// Pairs for row-tile it are contiguous: start = 2g(g+1) + (it&3)(g+1), g=it/4.
// ---------------------------------------------------------------------------
__global__ __launch_bounds__(256) void av_reduce_kernel(float* __restrict__ out)
{
    const int nt = blockIdx.x, it = blockIdx.y, b = blockIdx.z;
    const int g = it >> 2, nc = g + 1;
    const int start = 2 * g * (g + 1) + (it & 3) * nc;
    const int tid = threadIdx.x;

    __shared__ float rinv[128];
    if (tid < 128) {
        float s = 0.f;
        for (int pp = 0; pp < nc; pp++)
            s += g_prs[((size_t)b * NPAIR + start + pp) * 128 + tid];
        rinv[tid] = 1.0f / s;
    }
    __syncthreads();

    const int i0 = it * 128, n0 = nt * 128;
    const float4* pbase = (const float4*)(g_par);
    for (int e = tid; e < 4096; e += 256) {
        float4 s = make_float4(0.f, 0.f, 0.f, 0.f);
        for (int pp = 0; pp < nc; pp++) {
            const float4 v = pbase[(((size_t)b * NPAIR + start + pp) * 4 + nt) * 4096 + e];
            s.x += v.x; s.y += v.y; s.z += v.z; s.w += v.w;
        }
        const int row = e >> 5, col4 = (e & 31) * 4;
        const float inv = rinv[row];
        s.x *= inv; s.y *= inv; s.z *= inv; s.w *= inv;
        *(float4*)&out[((size_t)b * TT + i0 + row) * 1024 + 512 + n0 + col4] = s;
    }
}

// ---------------------------------------------------------------------------
extern "C" void kernel_launch(void* const* d_in, const int* in_sizes, int n_in,
                              void* d_out, int out_size)
{
    const float* x  = (const float*)d_in[0];
    const float* Wq = (const float*)d_in[1];
    const float* bq = (const float*)d_in[2];
    const float* Wk = (const float*)d_in[3];
    const float* bk = (const float*)d_in[4];
    const float* Wv = (const float*)d_in[5];
    const float* bv = (const float*)d_in[6];
    float* out = (float*)d_out;

    cudaFuncSetAttribute(proj_kernel,     cudaFuncAttributeMaxDynamicSharedMemorySize, GSMEM);
    cudaFuncSetAttribute(score_kernel,    cudaFuncAttributeMaxDynamicSharedMemorySize, GSMEM);
    cudaFuncSetAttribute(av_chunk_kernel, cudaFuncAttributeMaxDynamicSharedMemorySize, GSMEM);

    x2h_kernel<<<(MTOT * CC / 4) / 256, 256>>>((const float4*)x);
    wt_kernel<<<dim3(16, 16, 3), 256>>>(Wq, Wk, Wv);

    proj_kernel<<<dim3(4, 128, 3), 256, GSMEM>>>(bq, bk, bv);

    copy_x_kernel<<<(MTOT * 128) / 256, 256>>>((const float4*)x, (float4*)out);
    vt_kernel<<<dim3(32, 8, NB), 256>>>();

    score_kernel<<<dim3(16, 16, NB), 256, GSMEM>>>();
    av_chunk_kernel<<<dim3(4, NPAIR, NB), 256, GSMEM>>>();
    av_reduce_kernel<<<dim3(4, 16, NB), 256>>>(out);
}